// round 2
// baseline (speedup 1.0000x reference)
#include <cuda_runtime.h>
#include <cuda_bf16.h>
#include <cstdint>

// ---------------- Problem constants ----------------
#define BATCH   2048
#define NCOLS   32
#define CATD    2000
#define HID     128
#define VTOT    64000

// ---------------- Device scratch (no allocs allowed) ----------------
__device__ __align__(16) __nv_bfloat16 g_Wb[VTOT * HID];      // 16 MB  bf16 W_dec
__device__ __align__(16) float         g_c[VTOT];             // 256 KB c[v] = ybar . W_dec[v] + b_dec[v]
__device__ __align__(16) __nv_bfloat16 g_delta[BATCH * HID];  // 512 KB bf16 (y - ybar)

__device__ __forceinline__ uint32_t smem_to_u32(const void* p) {
    uint32_t a;
    asm("{ .reg .u64 t; cvta.to.shared.u64 t, %1; cvt.u32.u64 %0, t; }" : "=r"(a) : "l"(p));
    return a;
}

// ---------------- Kernel 1: prep — W_dec -> bf16, c[v] = ybar . W_dec[v] + b_dec[v] ----------------
__global__ void __launch_bounds__(256) prep_kernel(const float* __restrict__ Wdec,
                                                   const float* __restrict__ benc,
                                                   const float* __restrict__ bdec) {
    int gw   = (blockIdx.x * blockDim.x + threadIdx.x) >> 5;  // one warp per v row
    int lane = threadIdx.x & 31;
    if (gw >= VTOT) return;

    float4 w = *reinterpret_cast<const float4*>(Wdec + (size_t)gw * HID + lane * 4);

    float b0 = benc[lane * 4 + 0], b1 = benc[lane * 4 + 1];
    float b2 = benc[lane * 4 + 2], b3 = benc[lane * 4 + 3];
    float dot = w.x / (1.0f + expf(-b0)) + w.y / (1.0f + expf(-b1))
              + w.z / (1.0f + expf(-b2)) + w.w / (1.0f + expf(-b3));

    __nv_bfloat162 p0 = __floats2bfloat162_rn(w.x, w.y);
    __nv_bfloat162 p1 = __floats2bfloat162_rn(w.z, w.w);
    uint2 pk;
    pk.x = *reinterpret_cast<uint32_t*>(&p0);
    pk.y = *reinterpret_cast<uint32_t*>(&p1);
    *reinterpret_cast<uint2*>(g_Wb + (size_t)gw * HID + lane * 4) = pk;

    #pragma unroll
    for (int o = 16; o > 0; o >>= 1) dot += __shfl_xor_sync(0xffffffffu, dot, o);
    if (lane == 0) g_c[gw] = dot + bdec[gw];
}

// ---------------- Kernel 2: encode — y = sigmoid(gather-sum), delta = bf16(y - ybar) ----------------
__global__ void __launch_bounds__(128) encode_kernel(const int* __restrict__ xcat,
                                                     const float* __restrict__ Wenc,
                                                     const float* __restrict__ benc,
                                                     float* __restrict__ yout) {
    __shared__ int xi[NCOLS];
    int b = blockIdx.x;
    int h = threadIdx.x;
    if (h < NCOLS) xi[h] = xcat[b * NCOLS + h];
    __syncthreads();

    float be  = benc[h];
    float acc = be;
    const float* row = Wenc + (size_t)h * VTOT;
    #pragma unroll 8
    for (int i = 0; i < NCOLS; i++) acc += row[xi[i] + i * CATD];

    float y = 1.0f / (1.0f + expf(-acc));
    if (yout) yout[b * HID + h] = y;
    float ybar = 1.0f / (1.0f + expf(-be));
    g_delta[b * HID + h] = __float2bfloat16(y - ybar);
}

// ---------------- Kernel 3: decode GEMM — z = c[v] + delta . Wb^T (mma.sync bf16) ----------------
// CTA tile: 128 (M=batch) x 128 (N=vocab), K=128 in one shot.
// 8 warps: 2 (M) x 4 (N); warp tile 64x32 => 4 m-frags (16) x 4 n-frags (8), 8 k-steps (16).
// smem rows padded to 272B (128 bf16 + 8 pad) -> conflict-free ldmatrix.

#define TILE_M 128
#define TILE_N 128
#define SROWB  272                       // smem row stride in bytes
#define SM_A_OFF 0
#define SM_B_OFF (128 * SROWB)           // 34816
#define SM_TOTAL (2 * 128 * SROWB)       // 69632

__device__ __forceinline__ void ldmatrix_x4(uint32_t (&r)[4], uint32_t addr) {
    asm volatile("ldmatrix.sync.aligned.m8n8.x4.shared.b16 {%0,%1,%2,%3}, [%4];"
                 : "=r"(r[0]), "=r"(r[1]), "=r"(r[2]), "=r"(r[3]) : "r"(addr));
}
__device__ __forceinline__ void ldmatrix_x2(uint32_t (&r)[2], uint32_t addr) {
    asm volatile("ldmatrix.sync.aligned.m8n8.x2.shared.b16 {%0,%1}, [%2];"
                 : "=r"(r[0]), "=r"(r[1]) : "r"(addr));
}
__device__ __forceinline__ void mma_bf16(float (&d)[4], const uint32_t (&a)[4], const uint32_t (&b)[2]) {
    asm volatile(
        "mma.sync.aligned.m16n8k16.row.col.f32.bf16.bf16.f32 "
        "{%0,%1,%2,%3}, {%4,%5,%6,%7}, {%8,%9}, {%0,%1,%2,%3};"
        : "+f"(d[0]), "+f"(d[1]), "+f"(d[2]), "+f"(d[3])
        : "r"(a[0]), "r"(a[1]), "r"(a[2]), "r"(a[3]), "r"(b[0]), "r"(b[1]));
}

__global__ void __launch_bounds__(256) decode_gemm(float* __restrict__ zout) {
    extern __shared__ char smem[];
    int tid  = threadIdx.x;
    int wid  = tid >> 5;
    int lane = tid & 31;
    int mblk = blockIdx.x;   // 0..15
    int nblk = blockIdx.y;   // 0..499

    // ---- Load A (delta) and B (Wb) tiles: 128 rows x 256B each, padded rows ----
    const uint4* Asrc = reinterpret_cast<const uint4*>(g_delta + (size_t)mblk * TILE_M * HID);
    const uint4* Bsrc = reinterpret_cast<const uint4*>(g_Wb    + (size_t)nblk * TILE_N * HID);
    #pragma unroll
    for (int it = 0; it < 8; ++it) {
        int idx = it * 256 + tid;                  // 0..2047 uint4 chunks
        int row = idx >> 4;
        int ch  = idx & 15;
        *reinterpret_cast<uint4*>(smem + SM_A_OFF + row * SROWB + ch * 16) = Asrc[idx];
        *reinterpret_cast<uint4*>(smem + SM_B_OFF + row * SROWB + ch * 16) = Bsrc[idx];
    }
    __syncthreads();

    int wm = wid & 1;        // 0..1  (M)
    int wn = wid >> 1;       // 0..3  (N)

    uint32_t sbase = smem_to_u32(smem);
    // A ldmatrix base: row = wm*64 + (lane&15), col half = (lane>>4)*8 elems (=16B)
    uint32_t aBase = sbase + SM_A_OFF + (uint32_t)(wm * 64 + (lane & 15)) * SROWB + ((lane >> 4) << 4);
    // B ldmatrix base: row = wn*32 + (lane&7), col half = ((lane>>3)&1)*8 elems
    uint32_t bBase = sbase + SM_B_OFF + (uint32_t)(wn * 32 + (lane & 7)) * SROWB + (((lane >> 3) & 1) << 4);

    float acc[4][4][4];
    #pragma unroll
    for (int i = 0; i < 4; ++i)
        #pragma unroll
        for (int j = 0; j < 4; ++j)
            #pragma unroll
            for (int k = 0; k < 4; ++k) acc[i][j][k] = 0.0f;

    #pragma unroll
    for (int ks = 0; ks < 8; ++ks) {
        uint32_t a[4][4];
        uint32_t b[4][2];
        #pragma unroll
        for (int mf = 0; mf < 4; ++mf)
            ldmatrix_x4(a[mf], aBase + (uint32_t)mf * 16u * SROWB + (uint32_t)ks * 32u);
        #pragma unroll
        for (int nf = 0; nf < 4; ++nf)
            ldmatrix_x2(b[nf], bBase + (uint32_t)nf * 8u * SROWB + (uint32_t)ks * 32u);
        #pragma unroll
        for (int mf = 0; mf < 4; ++mf)
            #pragma unroll
            for (int nf = 0; nf < 4; ++nf)
                mma_bf16(acc[mf][nf], a[mf], b[nf]);
    }

    // ---- Epilogue: z = acc + c[v], float2 stores ----
    int colLoc = wn * 32 + (lane & 3) * 2;                  // within N tile
    const float* ctab = g_c + (size_t)nblk * TILE_N;
    float2 cv[4];
    #pragma unroll
    for (int nf = 0; nf < 4; ++nf)
        cv[nf] = *reinterpret_cast<const float2*>(ctab + colLoc + nf * 8);

    int rowBase = mblk * TILE_M + wm * 64 + (lane >> 2);
    size_t colG = (size_t)nblk * TILE_N + colLoc;
    #pragma unroll
    for (int mf = 0; mf < 4; ++mf) {
        float* z0 = zout + (size_t)(rowBase + mf * 16) * VTOT + colG;
        float* z1 = z0 + 8 * VTOT;
        #pragma unroll
        for (int nf = 0; nf < 4; ++nf) {
            float2 o0, o1;
            o0.x = acc[mf][nf][0] + cv[nf].x;
            o0.y = acc[mf][nf][1] + cv[nf].y;
            o1.x = acc[mf][nf][2] + cv[nf].x;
            o1.y = acc[mf][nf][3] + cv[nf].y;
            *reinterpret_cast<float2*>(z0 + nf * 8) = o0;
            *reinterpret_cast<float2*>(z1 + nf * 8) = o1;
        }
    }
}

// ---------------- Launch ----------------
extern "C" void kernel_launch(void* const* d_in, const int* in_sizes, int n_in,
                              void* d_out, int out_size) {
    const int*   xcat = (const int*)d_in[0];
    const float* Wenc = (const float*)d_in[1];
    const float* benc = (const float*)d_in[2];
    const float* Wdec = (const float*)d_in[3];
    const float* bdec = (const float*)d_in[4];

    float* out = (float*)d_out;
    long long ztotal = (long long)BATCH * VTOT;
    long long zoff   = (long long)out_size - ztotal;   // expected 2048*128
    if (zoff < 0) zoff = 0;
    float* zout = out + zoff;
    float* yout = (zoff >= (long long)BATCH * HID) ? out : nullptr;

    cudaFuncSetAttribute(decode_gemm, cudaFuncAttributeMaxDynamicSharedMemorySize, SM_TOTAL);

    prep_kernel<<<VTOT / 8, 256>>>(Wdec, benc, bdec);
    encode_kernel<<<BATCH, 128>>>(xcat, Wenc, benc, yout);
    decode_gemm<<<dim3(BATCH / TILE_M, VTOT / TILE_N), 256, SM_TOTAL>>>(zout);
}

// round 3
// speedup vs baseline: 1.0502x; 1.0502x over previous
#include <cuda_runtime.h>
#include <cuda_bf16.h>
#include <cstdint>

// ---------------- Problem constants ----------------
#define BATCH   2048
#define NCOLS   32
#define CATD    2000
#define HID     128
#define VTOT    64000

// ---------------- Device scratch (no allocs allowed) ----------------
__device__ __align__(16) __nv_bfloat16 g_Wb[VTOT * HID];      // 16 MB  bf16 W_dec
__device__ __align__(16) float         g_c[VTOT];             // 256 KB c[v] = ybar . W_dec[v] + b_dec[v]
__device__ __align__(16) __nv_bfloat16 g_delta[BATCH * HID];  // 512 KB bf16 (y - ybar)
__device__ __align__(16) float         g_WT[VTOT * HID];      // 32 MB  W_enc transposed [v][h]

__device__ __forceinline__ uint32_t smem_to_u32(const void* p) {
    uint32_t a;
    asm("{ .reg .u64 t; cvta.to.shared.u64 t, %1; cvt.u32.u64 %0, t; }" : "=r"(a) : "l"(p));
    return a;
}

#define CP_ASYNC_CG16(dst_smem, src_gmem) \
    asm volatile("cp.async.cg.shared.global [%0], [%1], 16;" \
        :: "r"(dst_smem), "l"(src_gmem) : "memory")
#define CP_ASYNC_COMMIT() asm volatile("cp.async.commit_group;" ::: "memory")
#define CP_ASYNC_WAIT(n)  asm volatile("cp.async.wait_group %0;" :: "n"(n) : "memory")

// ---------------- Kernel 0: transpose W_enc [HID,VTOT] -> g_WT [VTOT,HID] ----------------
__global__ void __launch_bounds__(256) transpose_kernel(const float* __restrict__ Wenc) {
    extern __shared__ float st[];              // [128 v][129] (padded)
    int v0 = blockIdx.x * 128;
    int t  = threadIdx.x;

    #pragma unroll
    for (int it = 0; it < 64; ++it) {          // 128h x 128v elements
        int idx = it * 256 + t;
        int v = idx & 127;
        int h = idx >> 7;
        st[v * 129 + h] = Wenc[(size_t)h * VTOT + v0 + v];
    }
    __syncthreads();
    #pragma unroll
    for (int it = 0; it < 16; ++it) {          // 4096 float4 writes
        int idx = it * 256 + t;
        int h4 = (idx & 31) * 4;
        int v  = idx >> 5;
        float4 o;
        o.x = st[v * 129 + h4 + 0];
        o.y = st[v * 129 + h4 + 1];
        o.z = st[v * 129 + h4 + 2];
        o.w = st[v * 129 + h4 + 3];
        *reinterpret_cast<float4*>(g_WT + (size_t)(v0 + v) * HID + h4) = o;
    }
}

// ---------------- Kernel 1: prep — W_dec -> bf16, c[v] = ybar . W_dec[v] + b_dec[v] ----------------
__global__ void __launch_bounds__(256) prep_kernel(const float* __restrict__ Wdec,
                                                   const float* __restrict__ benc,
                                                   const float* __restrict__ bdec) {
    int gw   = (blockIdx.x * blockDim.x + threadIdx.x) >> 5;  // one warp per v row
    int lane = threadIdx.x & 31;
    if (gw >= VTOT) return;

    float4 w = *reinterpret_cast<const float4*>(Wdec + (size_t)gw * HID + lane * 4);

    float b0 = benc[lane * 4 + 0], b1 = benc[lane * 4 + 1];
    float b2 = benc[lane * 4 + 2], b3 = benc[lane * 4 + 3];
    float dot = w.x / (1.0f + __expf(-b0)) + w.y / (1.0f + __expf(-b1))
              + w.z / (1.0f + __expf(-b2)) + w.w / (1.0f + __expf(-b3));

    __nv_bfloat162 p0 = __floats2bfloat162_rn(w.x, w.y);
    __nv_bfloat162 p1 = __floats2bfloat162_rn(w.z, w.w);
    uint2 pk;
    pk.x = *reinterpret_cast<uint32_t*>(&p0);
    pk.y = *reinterpret_cast<uint32_t*>(&p1);
    *reinterpret_cast<uint2*>(g_Wb + (size_t)gw * HID + lane * 4) = pk;

    #pragma unroll
    for (int o = 16; o > 0; o >>= 1) dot += __shfl_xor_sync(0xffffffffu, dot, o);
    if (lane == 0) g_c[gw] = dot + bdec[gw];
}

// ---------------- Kernel 2: encode — warp per batch item, coalesced rows of g_WT ----------------
__global__ void __launch_bounds__(256) encode_kernel(const int* __restrict__ xcat,
                                                     const float* __restrict__ benc,
                                                     float* __restrict__ yout) {
    int wid  = threadIdx.x >> 5;
    int lane = threadIdx.x & 31;
    int b    = blockIdx.x * 8 + wid;           // 256 blocks x 8 warps = 2048

    int gidx = xcat[b * NCOLS + lane] + lane * CATD;   // lane i holds global idx of col i

    float a0 = 0.f, a1 = 0.f, a2 = 0.f, a3 = 0.f;
    #pragma unroll
    for (int i = 0; i < NCOLS; ++i) {
        int gi = __shfl_sync(0xffffffffu, gidx, i);
        float4 w = *reinterpret_cast<const float4*>(g_WT + (size_t)gi * HID + lane * 4);
        a0 += w.x; a1 += w.y; a2 += w.z; a3 += w.w;
    }

    float4 be = *reinterpret_cast<const float4*>(benc + lane * 4);
    float y0 = 1.0f / (1.0f + __expf(-(a0 + be.x)));
    float y1 = 1.0f / (1.0f + __expf(-(a1 + be.y)));
    float y2 = 1.0f / (1.0f + __expf(-(a2 + be.z)));
    float y3 = 1.0f / (1.0f + __expf(-(a3 + be.w)));
    if (yout) {
        float4 yv = {y0, y1, y2, y3};
        *reinterpret_cast<float4*>(yout + (size_t)b * HID + lane * 4) = yv;
    }
    float d0 = y0 - 1.0f / (1.0f + __expf(-be.x));
    float d1 = y1 - 1.0f / (1.0f + __expf(-be.y));
    float d2 = y2 - 1.0f / (1.0f + __expf(-be.z));
    float d3 = y3 - 1.0f / (1.0f + __expf(-be.w));
    __nv_bfloat162 p0 = __floats2bfloat162_rn(d0, d1);
    __nv_bfloat162 p1 = __floats2bfloat162_rn(d2, d3);
    uint2 pk;
    pk.x = *reinterpret_cast<uint32_t*>(&p0);
    pk.y = *reinterpret_cast<uint32_t*>(&p1);
    *reinterpret_cast<uint2*>(g_delta + (size_t)b * HID + lane * 4) = pk;
}

// ---------------- Kernel 3: decode GEMM — z = c[v] + delta . Wb^T (mma.sync bf16) ----------------
// CTA tile 128x128, K=128 split into two 64-wide halves pipelined via cp.async.
// 8 warps: 2(M) x 4(N); warp tile 64x32.

#define TILE_M 128
#define TILE_N 128
#define SROWB  272                       // smem row stride in bytes (128 bf16 + 8 pad)
#define SM_A_OFF 0
#define SM_B_OFF (128 * SROWB)
#define SM_TOTAL (2 * 128 * SROWB)       // 69632

__device__ __forceinline__ void ldmatrix_x4(uint32_t (&r)[4], uint32_t addr) {
    asm volatile("ldmatrix.sync.aligned.m8n8.x4.shared.b16 {%0,%1,%2,%3}, [%4];"
                 : "=r"(r[0]), "=r"(r[1]), "=r"(r[2]), "=r"(r[3]) : "r"(addr));
}
__device__ __forceinline__ void mma_bf16(float (&d)[4], const uint32_t (&a)[4], const uint32_t* b) {
    asm volatile(
        "mma.sync.aligned.m16n8k16.row.col.f32.bf16.bf16.f32 "
        "{%0,%1,%2,%3}, {%4,%5,%6,%7}, {%8,%9}, {%0,%1,%2,%3};"
        : "+f"(d[0]), "+f"(d[1]), "+f"(d[2]), "+f"(d[3])
        : "r"(a[0]), "r"(a[1]), "r"(a[2]), "r"(a[3]), "r"(b[0]), "r"(b[1]));
}

__global__ void __launch_bounds__(256, 2) decode_gemm(float* __restrict__ zout) {
    extern __shared__ char smem[];
    uint32_t sbase = smem_to_u32(smem);
    int tid  = threadIdx.x;
    int wid  = tid >> 5;
    int lane = tid & 31;
    int mblk = blockIdx.x;   // 0..15
    int nblk = blockIdx.y;   // 0..499

    const char* Asrc = reinterpret_cast<const char*>(g_delta + (size_t)mblk * TILE_M * HID);
    const char* Bsrc = reinterpret_cast<const char*>(g_Wb    + (size_t)nblk * TILE_N * HID);

    // Pipelined tile load: half h covers K bytes [h*128, h*128+128) of every row.
    #pragma unroll
    for (int h = 0; h < 2; ++h) {
        #pragma unroll
        for (int it = 0; it < 4; ++it) {
            int idx = it * 256 + tid;               // 0..1023 chunks of 16B per tile-half
            int row = idx >> 3;
            int ch  = (idx & 7) * 16 + h * 128;
            CP_ASYNC_CG16(sbase + SM_A_OFF + row * SROWB + ch, Asrc + row * 256 + ch);
            CP_ASYNC_CG16(sbase + SM_B_OFF + row * SROWB + ch, Bsrc + row * 256 + ch);
        }
        CP_ASYNC_COMMIT();
    }

    int wm = wid & 1;        // M
    int wn = wid >> 1;       // N

    // Epilogue constants — load early, overlaps cp.async wait.
    int colLoc = wn * 32 + (lane & 3) * 2;
    const float* ctab = g_c + (size_t)nblk * TILE_N;
    float2 cv[4];
    #pragma unroll
    for (int nf = 0; nf < 4; ++nf)
        cv[nf] = *reinterpret_cast<const float2*>(ctab + colLoc + nf * 8);

    uint32_t aBase = sbase + SM_A_OFF + (uint32_t)(wm * 64 + (lane & 15)) * SROWB + ((lane >> 4) << 4);
    // B via x4: group g=lane>>3: row = pair*16 + (g>>1)*8 + (lane&7), col16 = (g&1)*16
    uint32_t bBase = sbase + SM_B_OFF
                   + (uint32_t)(wn * 32 + ((lane >> 4) << 3) + (lane & 7)) * SROWB
                   + (((lane >> 3) & 1) << 4);

    float acc[4][4][4];
    #pragma unroll
    for (int i = 0; i < 4; ++i)
        #pragma unroll
        for (int j = 0; j < 4; ++j)
            #pragma unroll
            for (int k = 0; k < 4; ++k) acc[i][j][k] = 0.0f;

    CP_ASYNC_WAIT(1);
    __syncthreads();

    #pragma unroll
    for (int half = 0; half < 2; ++half) {
        #pragma unroll
        for (int ks = 0; ks < 4; ++ks) {
            uint32_t koff = (uint32_t)(half * 4 + ks) * 32u;
            uint32_t a[4][4];
            uint32_t b[2][4];    // b[p] = {nf(2p) k0, nf(2p) k1, nf(2p+1) k0, nf(2p+1) k1}
            #pragma unroll
            for (int mf = 0; mf < 4; ++mf)
                ldmatrix_x4(a[mf], aBase + (uint32_t)mf * 16u * SROWB + koff);
            #pragma unroll
            for (int p = 0; p < 2; ++p)
                ldmatrix_x4(b[p], bBase + (uint32_t)p * 16u * SROWB + koff);
            #pragma unroll
            for (int mf = 0; mf < 4; ++mf)
                #pragma unroll
                for (int nf = 0; nf < 4; ++nf)
                    mma_bf16(acc[mf][nf], a[mf], &b[nf >> 1][(nf & 1) * 2]);
        }
        if (half == 0) {
            CP_ASYNC_WAIT(0);
            __syncthreads();
        }
    }

    // ---- Epilogue: z = acc + c[v], float2 stores ----
    int rowBase = mblk * TILE_M + wm * 64 + (lane >> 2);
    size_t colG = (size_t)nblk * TILE_N + colLoc;
    #pragma unroll
    for (int mf = 0; mf < 4; ++mf) {
        float* z0 = zout + (size_t)(rowBase + mf * 16) * VTOT + colG;
        float* z1 = z0 + 8 * VTOT;
        #pragma unroll
        for (int nf = 0; nf < 4; ++nf) {
            float2 o0, o1;
            o0.x = acc[mf][nf][0] + cv[nf].x;
            o0.y = acc[mf][nf][1] + cv[nf].y;
            o1.x = acc[mf][nf][2] + cv[nf].x;
            o1.y = acc[mf][nf][3] + cv[nf].y;
            *reinterpret_cast<float2*>(z0 + nf * 8) = o0;
            *reinterpret_cast<float2*>(z1 + nf * 8) = o1;
        }
    }
}

// ---------------- Launch ----------------
extern "C" void kernel_launch(void* const* d_in, const int* in_sizes, int n_in,
                              void* d_out, int out_size) {
    const int*   xcat = (const int*)d_in[0];
    const float* Wenc = (const float*)d_in[1];
    const float* benc = (const float*)d_in[2];
    const float* Wdec = (const float*)d_in[3];
    const float* bdec = (const float*)d_in[4];

    float* out = (float*)d_out;
    long long ztotal = (long long)BATCH * VTOT;
    long long zoff   = (long long)out_size - ztotal;   // expected 2048*128
    if (zoff < 0) zoff = 0;
    float* zout = out + zoff;
    float* yout = (zoff >= (long long)BATCH * HID) ? out : nullptr;

    static int attr_done = 0;
    if (!attr_done) {
        cudaFuncSetAttribute(decode_gemm, cudaFuncAttributeMaxDynamicSharedMemorySize, SM_TOTAL);
        cudaFuncSetAttribute(transpose_kernel, cudaFuncAttributeMaxDynamicSharedMemorySize, 128 * 129 * 4);
        attr_done = 1;
    }

    transpose_kernel<<<VTOT / 128, 256, 128 * 129 * 4>>>(Wenc);
    prep_kernel<<<VTOT / 8, 256>>>(Wdec, benc, bdec);
    encode_kernel<<<BATCH / 8, 256>>>(xcat, benc, yout);
    decode_gemm<<<dim3(BATCH / TILE_M, VTOT / TILE_N), 256, SM_TOTAL>>>(zout);
}

// round 4
// speedup vs baseline: 1.0755x; 1.0242x over previous
#include <cuda_runtime.h>
#include <cuda_bf16.h>
#include <cstdint>

// ---------------- Problem constants ----------------
#define BATCH   2048
#define NCOLS   32
#define CATD    2000
#define HID     128
#define VTOT    64000

// ---------------- Device scratch (no allocs allowed) ----------------
__device__ __align__(16) __nv_bfloat16 g_Wb[VTOT * HID];      // 16 MB  bf16 W_dec
__device__ __align__(16) float         g_c[VTOT];             // 256 KB c[v] = ybar . W_dec[v] + b_dec[v]
__device__ __align__(16) __nv_bfloat16 g_delta[BATCH * HID];  // 512 KB bf16 (y - ybar)
__device__ __align__(16) float         g_WT[VTOT * HID];      // 32 MB  W_enc transposed [v][h]

__device__ __forceinline__ uint32_t smem_to_u32(const void* p) {
    uint32_t a;
    asm("{ .reg .u64 t; cvta.to.shared.u64 t, %1; cvt.u32.u64 %0, t; }" : "=r"(a) : "l"(p));
    return a;
}

#define CP_ASYNC_CG16(dst_smem, src_gmem) \
    asm volatile("cp.async.cg.shared.global [%0], [%1], 16;" \
        :: "r"(dst_smem), "l"(src_gmem) : "memory")
#define CP_ASYNC_COMMIT() asm volatile("cp.async.commit_group;" ::: "memory")
#define CP_ASYNC_WAIT(n)  asm volatile("cp.async.wait_group %0;" :: "n"(n) : "memory")

// ---------------- Kernel 0: transpose W_enc [HID,VTOT] -> g_WT [VTOT,HID] ----------------
__global__ void __launch_bounds__(256) transpose_kernel(const float* __restrict__ Wenc) {
    extern __shared__ float st[];              // [128 v][129] (padded)
    int v0 = blockIdx.x * 128;
    int t  = threadIdx.x;

    #pragma unroll
    for (int it = 0; it < 64; ++it) {          // 128h x 128v elements
        int idx = it * 256 + t;
        int v = idx & 127;
        int h = idx >> 7;
        st[v * 129 + h] = Wenc[(size_t)h * VTOT + v0 + v];
    }
    __syncthreads();
    #pragma unroll
    for (int it = 0; it < 16; ++it) {          // 4096 float4 writes
        int idx = it * 256 + t;
        int h4 = (idx & 31) * 4;
        int v  = idx >> 5;
        float4 o;
        o.x = st[v * 129 + h4 + 0];
        o.y = st[v * 129 + h4 + 1];
        o.z = st[v * 129 + h4 + 2];
        o.w = st[v * 129 + h4 + 3];
        *reinterpret_cast<float4*>(g_WT + (size_t)(v0 + v) * HID + h4) = o;
    }
}

// ---------------- Kernel 1: prep — W_dec -> bf16, c[v] = ybar . W_dec[v] + b_dec[v] ----------------
__global__ void __launch_bounds__(256) prep_kernel(const float* __restrict__ Wdec,
                                                   const float* __restrict__ benc,
                                                   const float* __restrict__ bdec) {
    int gw   = (blockIdx.x * blockDim.x + threadIdx.x) >> 5;  // one warp per v row
    int lane = threadIdx.x & 31;
    if (gw >= VTOT) return;

    float4 w = *reinterpret_cast<const float4*>(Wdec + (size_t)gw * HID + lane * 4);

    float b0 = benc[lane * 4 + 0], b1 = benc[lane * 4 + 1];
    float b2 = benc[lane * 4 + 2], b3 = benc[lane * 4 + 3];
    float dot = w.x / (1.0f + __expf(-b0)) + w.y / (1.0f + __expf(-b1))
              + w.z / (1.0f + __expf(-b2)) + w.w / (1.0f + __expf(-b3));

    __nv_bfloat162 p0 = __floats2bfloat162_rn(w.x, w.y);
    __nv_bfloat162 p1 = __floats2bfloat162_rn(w.z, w.w);
    uint2 pk;
    pk.x = *reinterpret_cast<uint32_t*>(&p0);
    pk.y = *reinterpret_cast<uint32_t*>(&p1);
    *reinterpret_cast<uint2*>(g_Wb + (size_t)gw * HID + lane * 4) = pk;

    #pragma unroll
    for (int o = 16; o > 0; o >>= 1) dot += __shfl_xor_sync(0xffffffffu, dot, o);
    if (lane == 0) g_c[gw] = dot + bdec[gw];
}

// ---------------- Kernel 2: encode — warp per batch item, coalesced rows of g_WT ----------------
__global__ void __launch_bounds__(256) encode_kernel(const int* __restrict__ xcat,
                                                     const float* __restrict__ benc,
                                                     float* __restrict__ yout) {
    int wid  = threadIdx.x >> 5;
    int lane = threadIdx.x & 31;
    int b    = blockIdx.x * 8 + wid;           // 256 blocks x 8 warps = 2048

    int gidx = xcat[b * NCOLS + lane] + lane * CATD;   // lane i holds global idx of col i

    float a0 = 0.f, a1 = 0.f, a2 = 0.f, a3 = 0.f;
    #pragma unroll
    for (int i = 0; i < NCOLS; ++i) {
        int gi = __shfl_sync(0xffffffffu, gidx, i);
        float4 w = *reinterpret_cast<const float4*>(g_WT + (size_t)gi * HID + lane * 4);
        a0 += w.x; a1 += w.y; a2 += w.z; a3 += w.w;
    }

    float4 be = *reinterpret_cast<const float4*>(benc + lane * 4);
    float y0 = 1.0f / (1.0f + __expf(-(a0 + be.x)));
    float y1 = 1.0f / (1.0f + __expf(-(a1 + be.y)));
    float y2 = 1.0f / (1.0f + __expf(-(a2 + be.z)));
    float y3 = 1.0f / (1.0f + __expf(-(a3 + be.w)));
    if (yout) {
        float4 yv = {y0, y1, y2, y3};
        *reinterpret_cast<float4*>(yout + (size_t)b * HID + lane * 4) = yv;
    }
    float d0 = y0 - 1.0f / (1.0f + __expf(-be.x));
    float d1 = y1 - 1.0f / (1.0f + __expf(-be.y));
    float d2 = y2 - 1.0f / (1.0f + __expf(-be.z));
    float d3 = y3 - 1.0f / (1.0f + __expf(-be.w));
    __nv_bfloat162 p0 = __floats2bfloat162_rn(d0, d1);
    __nv_bfloat162 p1 = __floats2bfloat162_rn(d2, d3);
    uint2 pk;
    pk.x = *reinterpret_cast<uint32_t*>(&p0);
    pk.y = *reinterpret_cast<uint32_t*>(&p1);
    *reinterpret_cast<uint2*>(g_delta + (size_t)b * HID + lane * 4) = pk;
}

// ---------------- Kernel 3: decode GEMM — z = c[v] + delta . Wb^T (mma.sync bf16) ----------------
// Grid (16, NGRP): CTA (mblk, y) loads its 128x128 A tile ONCE, then walks
// nblks y, y+NGRP, ... with a double-buffered cp.async B pipeline.
// 8 warps: 2(M) x 4(N); warp tile 64x32; K=128 in 8 ksteps.

#define TILE_M 128
#define TILE_N 128
#define NGRP   18
#define NBLKS  (VTOT / TILE_N)           // 500
#define SROWB  272                       // smem row stride in bytes (128 bf16 + 8 pad)
#define TILE_BYTES (128 * SROWB)         // 34816
#define SM_A_OFF 0
#define SM_B_OFF TILE_BYTES
#define SM_TOTAL (3 * TILE_BYTES)        // 104448 (A + 2x B)

__device__ __forceinline__ void ldmatrix_x4(uint32_t (&r)[4], uint32_t addr) {
    asm volatile("ldmatrix.sync.aligned.m8n8.x4.shared.b16 {%0,%1,%2,%3}, [%4];"
                 : "=r"(r[0]), "=r"(r[1]), "=r"(r[2]), "=r"(r[3]) : "r"(addr));
}
__device__ __forceinline__ void mma_bf16(float (&d)[4], const uint32_t (&a)[4], const uint32_t* b) {
    asm volatile(
        "mma.sync.aligned.m16n8k16.row.col.f32.bf16.bf16.f32 "
        "{%0,%1,%2,%3}, {%4,%5,%6,%7}, {%8,%9}, {%0,%1,%2,%3};"
        : "+f"(d[0]), "+f"(d[1]), "+f"(d[2]), "+f"(d[3])
        : "r"(a[0]), "r"(a[1]), "r"(a[2]), "r"(a[3]), "r"(b[0]), "r"(b[1]));
}

__device__ __forceinline__ void load_B_tile(uint32_t sdst, const char* src, int tid) {
    #pragma unroll
    for (int it = 0; it < 8; ++it) {
        int idx = it * 256 + tid;                 // 0..2047 chunks of 16B
        int row = idx >> 4;
        int ch  = (idx & 15) * 16;
        CP_ASYNC_CG16(sdst + row * SROWB + ch, src + row * 256 + ch);
    }
}

__global__ void __launch_bounds__(256, 2) decode_gemm(float* __restrict__ zout) {
    extern __shared__ char smem[];
    uint32_t sbase = smem_to_u32(smem);
    int tid  = threadIdx.x;
    int wid  = tid >> 5;
    int lane = tid & 31;
    int mblk = blockIdx.x;   // 0..15
    int ygrp = blockIdx.y;   // 0..NGRP-1

    // ---- A tile once ----
    const char* Asrc = reinterpret_cast<const char*>(g_delta + (size_t)mblk * TILE_M * HID);
    #pragma unroll
    for (int it = 0; it < 8; ++it) {
        int idx = it * 256 + tid;
        int row = idx >> 4;
        int ch  = (idx & 15) * 16;
        CP_ASYNC_CG16(sbase + SM_A_OFF + row * SROWB + ch, Asrc + row * 256 + ch);
    }
    // ---- first B tile ----
    int nb = ygrp;
    load_B_tile(sbase + SM_B_OFF, reinterpret_cast<const char*>(g_Wb + (size_t)nb * TILE_N * HID), tid);
    CP_ASYNC_COMMIT();

    int wm = wid & 1;        // M
    int wn = wid >> 1;       // N
    int colLoc = wn * 32 + (lane & 3) * 2;

    uint32_t aBase = sbase + SM_A_OFF + (uint32_t)(wm * 64 + (lane & 15)) * SROWB + ((lane >> 4) << 4);
    uint32_t bOff  = (uint32_t)(wn * 32 + ((lane >> 4) << 3) + (lane & 7)) * SROWB
                   + (((lane >> 3) & 1) << 4);
    int rowBase = mblk * TILE_M + wm * 64 + (lane >> 2);

    CP_ASYNC_WAIT(0);
    __syncthreads();

    int buf = 0;
    while (true) {
        int nbn = nb + NGRP;
        bool more = (nbn < NBLKS);
        if (more) {
            load_B_tile(sbase + SM_B_OFF + (buf ^ 1) * TILE_BYTES,
                        reinterpret_cast<const char*>(g_Wb + (size_t)nbn * TILE_N * HID), tid);
            CP_ASYNC_COMMIT();
        }

        // epilogue constants for this tile (overlaps with MMA issue)
        const float* ctab = g_c + (size_t)nb * TILE_N;
        float2 cv[4];
        #pragma unroll
        for (int nf = 0; nf < 4; ++nf)
            cv[nf] = *reinterpret_cast<const float2*>(ctab + colLoc + nf * 8);

        float acc[4][4][4];
        #pragma unroll
        for (int i = 0; i < 4; ++i)
            #pragma unroll
            for (int j = 0; j < 4; ++j)
                #pragma unroll
                for (int k = 0; k < 4; ++k) acc[i][j][k] = 0.0f;

        uint32_t bBase = sbase + SM_B_OFF + (uint32_t)buf * TILE_BYTES + bOff;
        #pragma unroll
        for (int ks = 0; ks < 8; ++ks) {
            uint32_t koff = (uint32_t)ks * 32u;
            uint32_t a[4][4];
            uint32_t b[2][4];
            #pragma unroll
            for (int mf = 0; mf < 4; ++mf)
                ldmatrix_x4(a[mf], aBase + (uint32_t)mf * 16u * SROWB + koff);
            #pragma unroll
            for (int p = 0; p < 2; ++p)
                ldmatrix_x4(b[p], bBase + (uint32_t)p * 16u * SROWB + koff);
            #pragma unroll
            for (int mf = 0; mf < 4; ++mf)
                #pragma unroll
                for (int nf = 0; nf < 4; ++nf)
                    mma_bf16(acc[mf][nf], a[mf], &b[nf >> 1][(nf & 1) * 2]);
        }

        // ---- store this tile ----
        size_t colG = (size_t)nb * TILE_N + colLoc;
        #pragma unroll
        for (int mf = 0; mf < 4; ++mf) {
            float* z0 = zout + (size_t)(rowBase + mf * 16) * VTOT + colG;
            float* z1 = z0 + 8 * VTOT;
            #pragma unroll
            for (int nf = 0; nf < 4; ++nf) {
                float2 o0, o1;
                o0.x = acc[mf][nf][0] + cv[nf].x;
                o0.y = acc[mf][nf][1] + cv[nf].y;
                o1.x = acc[mf][nf][2] + cv[nf].x;
                o1.y = acc[mf][nf][3] + cv[nf].y;
                *reinterpret_cast<float2*>(z0 + nf * 8) = o0;
                *reinterpret_cast<float2*>(z1 + nf * 8) = o1;
            }
        }

        if (!more) break;
        CP_ASYNC_WAIT(0);
        __syncthreads();
        buf ^= 1;
        nb = nbn;
    }
}

// ---------------- Launch ----------------
extern "C" void kernel_launch(void* const* d_in, const int* in_sizes, int n_in,
                              void* d_out, int out_size) {
    const int*   xcat = (const int*)d_in[0];
    const float* Wenc = (const float*)d_in[1];
    const float* benc = (const float*)d_in[2];
    const float* Wdec = (const float*)d_in[3];
    const float* bdec = (const float*)d_in[4];

    float* out = (float*)d_out;
    long long ztotal = (long long)BATCH * VTOT;
    long long zoff   = (long long)out_size - ztotal;   // expected 2048*128
    if (zoff < 0) zoff = 0;
    float* zout = out + zoff;
    float* yout = (zoff >= (long long)BATCH * HID) ? out : nullptr;

    cudaFuncSetAttribute(decode_gemm, cudaFuncAttributeMaxDynamicSharedMemorySize, SM_TOTAL);
    cudaFuncSetAttribute(transpose_kernel, cudaFuncAttributeMaxDynamicSharedMemorySize, 128 * 129 * 4);

    transpose_kernel<<<VTOT / 128, 256, 128 * 129 * 4>>>(Wenc);
    prep_kernel<<<VTOT / 8, 256>>>(Wdec, benc, bdec);
    encode_kernel<<<BATCH / 8, 256>>>(xcat, benc, yout);
    decode_gemm<<<dim3(BATCH / TILE_M, NGRP), 256, SM_TOTAL>>>(zout);
}

// round 5
// speedup vs baseline: 1.2419x; 1.1547x over previous
#include <cuda_runtime.h>
#include <cuda_bf16.h>
#include <cstdint>

// ---------------- Problem constants ----------------
#define BATCH   2048
#define NCOLS   32
#define CATD    2000
#define HID     128
#define VTOT    64000

// ---------------- Device scratch (no allocs allowed) ----------------
__device__ __align__(16) __nv_bfloat16 g_Wb[VTOT * HID];      // 16 MB  bf16 W_dec
__device__ __align__(16) float         g_c[VTOT];             // 256 KB c[v] = ybar . W_dec[v] + b_dec[v]
__device__ __align__(16) __nv_bfloat16 g_delta[BATCH * HID];  // 512 KB bf16 (y - ybar)
__device__ __align__(16) float         g_WT[VTOT * HID];      // 32 MB  W_enc transposed [v][h]

__device__ __forceinline__ uint32_t smem_to_u32(const void* p) {
    uint32_t a;
    asm("{ .reg .u64 t; cvta.to.shared.u64 t, %1; cvt.u32.u64 %0, t; }" : "=r"(a) : "l"(p));
    return a;
}

#define CP_ASYNC_CG16(dst_smem, src_gmem) \
    asm volatile("cp.async.cg.shared.global [%0], [%1], 16;" \
        :: "r"(dst_smem), "l"(src_gmem) : "memory")
#define CP_ASYNC_COMMIT() asm volatile("cp.async.commit_group;" ::: "memory")
#define CP_ASYNC_WAIT(n)  asm volatile("cp.async.wait_group %0;" :: "n"(n) : "memory")

__device__ __forceinline__ void stg_cs_v4(float* p, float x, float y, float z, float w) {
    asm volatile("st.global.cs.v4.f32 [%0], {%1,%2,%3,%4};"
                 :: "l"(p), "f"(x), "f"(y), "f"(z), "f"(w) : "memory");
}

// ---------------- Kernel 0: fused transpose (W_enc -> g_WT) + prep (W_dec -> bf16, c[v]) --------
// blocks [0, 500): transpose 128-col slab; blocks [500, 500+8000): prep (8 rows each).
#define TP_BLOCKS (VTOT / 128)        // 500
#define PREP_BLOCKS (VTOT / 8)        // 8000

__global__ void __launch_bounds__(256) pre_kernel(const float* __restrict__ Wenc,
                                                  const float* __restrict__ Wdec,
                                                  const float* __restrict__ benc,
                                                  const float* __restrict__ bdec) {
    if (blockIdx.x < TP_BLOCKS) {
        // ---- transpose ----
        __shared__ float st[128 * 129];
        int v0 = blockIdx.x * 128;
        int t  = threadIdx.x;
        #pragma unroll
        for (int it = 0; it < 64; ++it) {
            int idx = it * 256 + t;
            int v = idx & 127;
            int h = idx >> 7;
            st[v * 129 + h] = Wenc[(size_t)h * VTOT + v0 + v];
        }
        __syncthreads();
        #pragma unroll
        for (int it = 0; it < 16; ++it) {
            int idx = it * 256 + t;
            int h4 = (idx & 31) * 4;
            int v  = idx >> 5;
            float4 o;
            o.x = st[v * 129 + h4 + 0];
            o.y = st[v * 129 + h4 + 1];
            o.z = st[v * 129 + h4 + 2];
            o.w = st[v * 129 + h4 + 3];
            *reinterpret_cast<float4*>(g_WT + (size_t)(v0 + v) * HID + h4) = o;
        }
    } else {
        // ---- prep: one warp per W_dec row ----
        int gw   = ((blockIdx.x - TP_BLOCKS) * 256 + threadIdx.x) >> 5;
        int lane = threadIdx.x & 31;
        if (gw >= VTOT) return;

        float4 w = *reinterpret_cast<const float4*>(Wdec + (size_t)gw * HID + lane * 4);

        float b0 = benc[lane * 4 + 0], b1 = benc[lane * 4 + 1];
        float b2 = benc[lane * 4 + 2], b3 = benc[lane * 4 + 3];
        float dot = w.x / (1.0f + __expf(-b0)) + w.y / (1.0f + __expf(-b1))
                  + w.z / (1.0f + __expf(-b2)) + w.w / (1.0f + __expf(-b3));

        __nv_bfloat162 p0 = __floats2bfloat162_rn(w.x, w.y);
        __nv_bfloat162 p1 = __floats2bfloat162_rn(w.z, w.w);
        uint2 pk;
        pk.x = *reinterpret_cast<uint32_t*>(&p0);
        pk.y = *reinterpret_cast<uint32_t*>(&p1);
        *reinterpret_cast<uint2*>(g_Wb + (size_t)gw * HID + lane * 4) = pk;

        #pragma unroll
        for (int o = 16; o > 0; o >>= 1) dot += __shfl_xor_sync(0xffffffffu, dot, o);
        if (lane == 0) g_c[gw] = dot + bdec[gw];
    }
}

// ---------------- Kernel 2: encode — warp per batch item, coalesced rows of g_WT ----------------
__global__ void __launch_bounds__(256) encode_kernel(const int* __restrict__ xcat,
                                                     const float* __restrict__ benc,
                                                     float* __restrict__ yout) {
    int wid  = threadIdx.x >> 5;
    int lane = threadIdx.x & 31;
    int b    = blockIdx.x * 8 + wid;

    int gidx = xcat[b * NCOLS + lane] + lane * CATD;

    float a0 = 0.f, a1 = 0.f, a2 = 0.f, a3 = 0.f;
    #pragma unroll
    for (int i = 0; i < NCOLS; ++i) {
        int gi = __shfl_sync(0xffffffffu, gidx, i);
        float4 w = *reinterpret_cast<const float4*>(g_WT + (size_t)gi * HID + lane * 4);
        a0 += w.x; a1 += w.y; a2 += w.z; a3 += w.w;
    }

    float4 be = *reinterpret_cast<const float4*>(benc + lane * 4);
    float y0 = 1.0f / (1.0f + __expf(-(a0 + be.x)));
    float y1 = 1.0f / (1.0f + __expf(-(a1 + be.y)));
    float y2 = 1.0f / (1.0f + __expf(-(a2 + be.z)));
    float y3 = 1.0f / (1.0f + __expf(-(a3 + be.w)));
    if (yout) {
        float4 yv = {y0, y1, y2, y3};
        *reinterpret_cast<float4*>(yout + (size_t)b * HID + lane * 4) = yv;
    }
    float d0 = y0 - 1.0f / (1.0f + __expf(-be.x));
    float d1 = y1 - 1.0f / (1.0f + __expf(-be.y));
    float d2 = y2 - 1.0f / (1.0f + __expf(-be.z));
    float d3 = y3 - 1.0f / (1.0f + __expf(-be.w));
    __nv_bfloat162 p0 = __floats2bfloat162_rn(d0, d1);
    __nv_bfloat162 p1 = __floats2bfloat162_rn(d2, d3);
    uint2 pk;
    pk.x = *reinterpret_cast<uint32_t*>(&p0);
    pk.y = *reinterpret_cast<uint32_t*>(&p1);
    *reinterpret_cast<uint2*>(g_delta + (size_t)b * HID + lane * 4) = pk;
}

// ---------------- Kernel 3: decode GEMM — z = c[v] + delta . Wb^T (mma.sync bf16) ----------------
// Persistent over N: grid (16, NGRP); A tile loaded once, B double-buffered via cp.async.
// B rows are PERMUTED within each 16-row group so that the mma C-fragment columns of a
// thread across a fragment pair are 4 consecutive globals -> STG.128 epilogue.
//   global col g (mod 16): q=g>>2, r=g&3; slot = r<2 ? 2q+r : 8+2q+(r&1)

#define TILE_M 128
#define TILE_N 128
#define NGRP   18
#define NBLKS  (VTOT / TILE_N)           // 500
#define SROWB  272
#define TILE_BYTES (128 * SROWB)         // 34816
#define SM_A_OFF 0
#define SM_B_OFF TILE_BYTES
#define SM_TOTAL (3 * TILE_BYTES)        // 104448

__device__ __forceinline__ void ldmatrix_x4(uint32_t (&r)[4], uint32_t addr) {
    asm volatile("ldmatrix.sync.aligned.m8n8.x4.shared.b16 {%0,%1,%2,%3}, [%4];"
                 : "=r"(r[0]), "=r"(r[1]), "=r"(r[2]), "=r"(r[3]) : "r"(addr));
}
__device__ __forceinline__ void mma_bf16(float (&d)[4], const uint32_t (&a)[4], const uint32_t* b) {
    asm volatile(
        "mma.sync.aligned.m16n8k16.row.col.f32.bf16.bf16.f32 "
        "{%0,%1,%2,%3}, {%4,%5,%6,%7}, {%8,%9}, {%0,%1,%2,%3};"
        : "+f"(d[0]), "+f"(d[1]), "+f"(d[2]), "+f"(d[3])
        : "r"(a[0]), "r"(a[1]), "r"(a[2]), "r"(a[3]), "r"(b[0]), "r"(b[1]));
}

__device__ __forceinline__ void load_B_tile(uint32_t sdst, const char* src, int tid) {
    #pragma unroll
    for (int it = 0; it < 8; ++it) {
        int idx = it * 256 + tid;                 // 0..2047 chunks of 16B
        int row = idx >> 4;
        int ch  = (idx & 15) * 16;
        int gg  = row & 15;
        int q   = gg >> 2, r = gg & 3;
        int slot = (r < 2) ? (q * 2 + r) : (8 + q * 2 + (r & 1));
        int prow = (row & ~15) | slot;
        CP_ASYNC_CG16(sdst + prow * SROWB + ch, src + row * 256 + ch);
    }
}

__global__ void __launch_bounds__(256, 2) decode_gemm(float* __restrict__ zout) {
    extern __shared__ char smem[];
    uint32_t sbase = smem_to_u32(smem);
    int tid  = threadIdx.x;
    int wid  = tid >> 5;
    int lane = tid & 31;
    int mblk = blockIdx.x;   // 0..15
    int ygrp = blockIdx.y;   // 0..NGRP-1

    // ---- A tile once (no permutation) ----
    const char* Asrc = reinterpret_cast<const char*>(g_delta + (size_t)mblk * TILE_M * HID);
    #pragma unroll
    for (int it = 0; it < 8; ++it) {
        int idx = it * 256 + tid;
        int row = idx >> 4;
        int ch  = (idx & 15) * 16;
        CP_ASYNC_CG16(sbase + SM_A_OFF + row * SROWB + ch, Asrc + row * 256 + ch);
    }
    int nb = ygrp;
    load_B_tile(sbase + SM_B_OFF, reinterpret_cast<const char*>(g_Wb + (size_t)nb * TILE_N * HID), tid);
    CP_ASYNC_COMMIT();

    int wm = wid & 1;        // M
    int wn = wid >> 1;       // N
    int j  = lane & 3;
    int colLoc = wn * 32 + j * 4;     // thread's first of 4 consecutive cols (pair 0)

    uint32_t aBase = sbase + SM_A_OFF + (uint32_t)(wm * 64 + (lane & 15)) * SROWB + ((lane >> 4) << 4);
    uint32_t bOff  = (uint32_t)(wn * 32 + ((lane >> 4) << 3) + (lane & 7)) * SROWB
                   + (((lane >> 3) & 1) << 4);
    int rowBase = mblk * TILE_M + wm * 64 + (lane >> 2);

    CP_ASYNC_WAIT(0);
    __syncthreads();

    int buf = 0;
    while (true) {
        int nbn = nb + NGRP;
        bool more = (nbn < NBLKS);
        if (more) {
            load_B_tile(sbase + SM_B_OFF + (buf ^ 1) * TILE_BYTES,
                        reinterpret_cast<const char*>(g_Wb + (size_t)nbn * TILE_N * HID), tid);
            CP_ASYNC_COMMIT();
        }

        const float* ctab = g_c + (size_t)nb * TILE_N;
        float4 cv[2];
        cv[0] = *reinterpret_cast<const float4*>(ctab + colLoc);
        cv[1] = *reinterpret_cast<const float4*>(ctab + colLoc + 16);

        float acc[4][4][4];
        #pragma unroll
        for (int i = 0; i < 4; ++i)
            #pragma unroll
            for (int jj = 0; jj < 4; ++jj)
                #pragma unroll
                for (int k = 0; k < 4; ++k) acc[i][jj][k] = 0.0f;

        uint32_t bBase = sbase + SM_B_OFF + (uint32_t)buf * TILE_BYTES + bOff;
        #pragma unroll
        for (int ks = 0; ks < 8; ++ks) {
            uint32_t koff = (uint32_t)ks * 32u;
            uint32_t a[4][4];
            uint32_t b[2][4];
            #pragma unroll
            for (int mf = 0; mf < 4; ++mf)
                ldmatrix_x4(a[mf], aBase + (uint32_t)mf * 16u * SROWB + koff);
            #pragma unroll
            for (int p = 0; p < 2; ++p)
                ldmatrix_x4(b[p], bBase + (uint32_t)p * 16u * SROWB + koff);
            #pragma unroll
            for (int mf = 0; mf < 4; ++mf)
                #pragma unroll
                for (int nf = 0; nf < 4; ++nf)
                    mma_bf16(acc[mf][nf], a[mf], &b[nf >> 1][(nf & 1) * 2]);
        }

        // ---- STG.128 streaming epilogue ----
        size_t colG = (size_t)nb * TILE_N + colLoc;
        #pragma unroll
        for (int mf = 0; mf < 4; ++mf) {
            float* z0 = zout + (size_t)(rowBase + mf * 16) * VTOT + colG;
            float* z1 = z0 + 8 * VTOT;
            #pragma unroll
            for (int p = 0; p < 2; ++p) {
                stg_cs_v4(z0 + p * 16,
                          acc[mf][2 * p][0] + cv[p].x, acc[mf][2 * p][1] + cv[p].y,
                          acc[mf][2 * p + 1][0] + cv[p].z, acc[mf][2 * p + 1][1] + cv[p].w);
                stg_cs_v4(z1 + p * 16,
                          acc[mf][2 * p][2] + cv[p].x, acc[mf][2 * p][3] + cv[p].y,
                          acc[mf][2 * p + 1][2] + cv[p].z, acc[mf][2 * p + 1][3] + cv[p].w);
            }
        }

        if (!more) break;
        CP_ASYNC_WAIT(0);
        __syncthreads();
        buf ^= 1;
        nb = nbn;
    }
}

// ---------------- Launch ----------------
extern "C" void kernel_launch(void* const* d_in, const int* in_sizes, int n_in,
                              void* d_out, int out_size) {
    const int*   xcat = (const int*)d_in[0];
    const float* Wenc = (const float*)d_in[1];
    const float* benc = (const float*)d_in[2];
    const float* Wdec = (const float*)d_in[3];
    const float* bdec = (const float*)d_in[4];

    float* out = (float*)d_out;
    long long ztotal = (long long)BATCH * VTOT;
    long long zoff   = (long long)out_size - ztotal;
    if (zoff < 0) zoff = 0;
    float* zout = out + zoff;
    float* yout = (zoff >= (long long)BATCH * HID) ? out : nullptr;

    cudaFuncSetAttribute(decode_gemm, cudaFuncAttributeMaxDynamicSharedMemorySize, SM_TOTAL);

    pre_kernel<<<TP_BLOCKS + PREP_BLOCKS, 256>>>(Wenc, Wdec, benc, bdec);
    encode_kernel<<<BATCH / 8, 256>>>(xcat, benc, yout);
    decode_gemm<<<dim3(BATCH / TILE_M, NGRP), 256, SM_TOTAL>>>(zout);
}